// round 4
// baseline (speedup 1.0000x reference)
#include <cuda_runtime.h>
#include <math.h>
#include <stdint.h>

// L = 1 collapses the Mamba scan: h = dBu, y = dt*xin*(Bm.Cm) + D*xin, A_log dead.
#define BB      512
#define DMODEL  512
#define DSTATE  128
#define DINNER  1024
#define DTRANK  32
#define HIDDEN  256
#define XDBL_W  (DTRANK + 2*DSTATE)   // 288

// -------- scratch (no allocations allowed; __device__ globals) --------
__device__ float g_xin [BB*DINNER];
__device__ float g_zsil[BB*DINNER];
__device__ float g_xdbl[BB*XDBL_W];
__device__ float g_y   [BB*DINNER];
__device__ float g_out1[BB*DMODEL];
__device__ float g_h1  [BB*HIDDEN];

__device__ __forceinline__ float siluf(float x) { return x / (1.f + __expf(-x)); }

__device__ __forceinline__ void mma_tf32(float c[4],
                                         unsigned a0, unsigned a1, unsigned a2, unsigned a3,
                                         unsigned b0, unsigned b1)
{
    asm volatile(
        "mma.sync.aligned.m16n8k8.row.col.f32.tf32.tf32.f32 "
        "{%0,%1,%2,%3}, {%4,%5,%6,%7}, {%8,%9}, {%0,%1,%2,%3};"
        : "+f"(c[0]), "+f"(c[1]), "+f"(c[2]), "+f"(c[3])
        : "r"(a0), "r"(a1), "r"(a2), "r"(a3), "r"(b0), "r"(b1));
}

__device__ __forceinline__ void cp16(void* smem, const void* gmem)
{
    unsigned sa = (unsigned)__cvta_generic_to_shared(smem);
    asm volatile("cp.async.cg.shared.global [%0], [%1], 16;" :: "r"(sa), "l"(gmem));
}

// ---------------------------------------------------------------------
// tf32 GEMM, 3-stage cp.async, 1 sync/iter: C[M,N] = A[M,K] @ W[N,K]^T.
// BM=64, BN=32, BK=32. 128 threads = 4 warps (2m x 2n).
// Warp tile 32x16 -> MT=2, NT=2 = 4 independent MMA chains (ILP).
// MODE 0: plain store
// MODE 1: + bias(aux0), leaky-relu 0.1
// MODE 2: in_proj split (n<DINNER -> silu(conv_b + conv_w[:,1]*v); else silu -> out2)
// MODE 3: inline bc = Bm.Cm; dt = softplus(v+aux0); C=(dt*xin*bc + aux1*xin)*zsil
// Requires M%64==0, N%32==0, K%32==0 (all shapes comply).
// ---------------------------------------------------------------------
template<int MODE>
__global__ void __launch_bounds__(128)
gemm_v4(const float* __restrict__ A, int lda,
        const float* __restrict__ W,
        float* __restrict__ C,
        int N, int K,
        const float* __restrict__ aux0,
        const float* __restrict__ aux1,
        float* __restrict__ out2)
{
    constexpr int BM  = 64;
    constexpr int BN  = 32;
    constexpr int BK  = 32;
    constexpr int LDS = BK + 4;        // stride 36: bank = base + 4g + t, conflict-free
    constexpr int NST = 3;

    __shared__ float As[NST][BM][LDS];
    __shared__ float Ws[NST][BN][LDS];
    __shared__ float sbc[BM];

    const int tid  = threadIdx.x;
    const int lane = tid & 31;
    const int wid  = tid >> 5;         // 0..3
    const int wm   = wid & 1;          // 2 warps along m
    const int wn   = wid >> 1;         // 2 warps along n
    const int g    = lane >> 2;        // 0..7
    const int t    = lane & 3;         // 0..3
    const int m0   = blockIdx.y * BM;
    const int n0   = blockIdx.x * BN;

    // cp.async thread mapping: 8 float4-chunks per row (BK=32)
    const int arow = tid >> 3;         // 0..15
    const int acol = (tid & 7) * 4;    // 0,4,...,28

    // MODE3: per-row bc = dot(Bm, Cm) from g_xdbl rows (lda == XDBL_W)
    if (MODE == 3) {
        #pragma unroll
        for (int rr = 0; rr < 16; ++rr) {
            const int r = wid * 16 + rr;
            const float* row = &A[(m0 + r) * XDBL_W];
            float v = 0.f;
            #pragma unroll
            for (int i = 0; i < DSTATE / 32; ++i)
                v += row[DTRANK + lane + 32*i] * row[DTRANK + DSTATE + lane + 32*i];
            #pragma unroll
            for (int o = 16; o > 0; o >>= 1) v += __shfl_xor_sync(0xFFFFFFFFu, v, o);
            if (lane == 0) sbc[r] = v;
        }
    }

    const int NK = K / BK;

    auto load_tiles = [&](int kt, int buf) {
        const int k0 = kt * BK;
        #pragma unroll
        for (int r = 0; r < 4; ++r)    // A: 64 rows, 16 rows/round
            cp16(&As[buf][arow + 16*r][acol], &A[(m0 + arow + 16*r) * lda + k0 + acol]);
        #pragma unroll
        for (int r = 0; r < 2; ++r)    // W: 32 rows
            cp16(&Ws[buf][arow + 16*r][acol], &W[(n0 + arow + 16*r) * K + k0 + acol]);
    };

    float acc[2][2][4] = {};

    load_tiles(0, 0);
    asm volatile("cp.async.commit_group;");
    if (NK > 1) {
        load_tiles(1, 1);
        asm volatile("cp.async.commit_group;");
    }

    for (int it = 0; it < NK; ++it) {
        if (it + 1 < NK) asm volatile("cp.async.wait_group 1;");
        else             asm volatile("cp.async.wait_group 0;");
        __syncthreads();               // stage 'it' visible; compute(it-1) done by all

        if (it + 2 < NK) {             // safe: overwrites buffer computed at it-1
            load_tiles(it + 2, (it + 2) % NST);
            asm volatile("cp.async.commit_group;");
        }

        const int buf = it % NST;
        #pragma unroll
        for (int ks = 0; ks < BK / 8; ++ks) {
            const int kk = ks * 8 + t;
            unsigned b0[2], b1[2];
            #pragma unroll
            for (int nt = 0; nt < 2; ++nt) {
                const int br = wn * 16 + nt * 8 + g;
                b0[nt] = __float_as_uint(Ws[buf][br][kk]);
                b1[nt] = __float_as_uint(Ws[buf][br][kk + 4]);
            }
            #pragma unroll
            for (int mt = 0; mt < 2; ++mt) {
                const int ar = wm * 32 + mt * 16 + g;
                unsigned a0 = __float_as_uint(As[buf][ar    ][kk]);
                unsigned a1 = __float_as_uint(As[buf][ar + 8][kk]);
                unsigned a2 = __float_as_uint(As[buf][ar    ][kk + 4]);
                unsigned a3 = __float_as_uint(As[buf][ar + 8][kk + 4]);
                #pragma unroll
                for (int nt = 0; nt < 2; ++nt)
                    mma_tf32(acc[mt][nt], a0, a1, a2, a3, b0[nt], b1[nt]);
            }
        }
        // no trailing sync: next iter's sync orders buffer reuse
    }

    // ---- epilogue (float2: c0,c1 @ (m,nb); c2,c3 @ (m+8,nb)) ----
    #pragma unroll
    for (int mt = 0; mt < 2; ++mt) {
        #pragma unroll
        for (int nt = 0; nt < 2; ++nt) {
            const int nb = n0 + wn * 16 + nt * 8 + 2 * t;
            #pragma unroll
            for (int half = 0; half < 2; ++half) {
                const int m = m0 + wm * 32 + mt * 16 + g + 8 * half;
                float v0 = acc[mt][nt][2*half + 0];
                float v1 = acc[mt][nt][2*half + 1];
                if (MODE == 0) {
                    *reinterpret_cast<float2*>(&C[m * N + nb]) = make_float2(v0, v1);
                } else if (MODE == 1) {
                    v0 += aux0[nb]; v1 += aux0[nb + 1];
                    v0 = (v0 >= 0.f) ? v0 : 0.1f * v0;
                    v1 = (v1 >= 0.f) ? v1 : 0.1f * v1;
                    *reinterpret_cast<float2*>(&C[m * N + nb]) = make_float2(v0, v1);
                } else if (MODE == 2) {
                    if (n0 < DINNER) {   // uniform per CTA (1024 % 32 == 0)
                        float c0 = aux0[nb]     + aux1[2*nb + 1]     * v0;
                        float c1 = aux0[nb + 1] + aux1[2*(nb+1) + 1] * v1;
                        *reinterpret_cast<float2*>(&C[m * DINNER + nb]) =
                            make_float2(siluf(c0), siluf(c1));
                    } else {
                        *reinterpret_cast<float2*>(&out2[m * DINNER + nb - DINNER]) =
                            make_float2(siluf(v0), siluf(v1));
                    }
                } else { // MODE 3
                    v0 += aux0[nb]; v1 += aux0[nb + 1];
                    float dt0 = (v0 > 20.f) ? v0 : log1pf(__expf(v0));
                    float dt1 = (v1 > 20.f) ? v1 : log1pf(__expf(v1));
                    float2 xv = *reinterpret_cast<const float2*>(&g_xin [m * DINNER + nb]);
                    float2 zv = *reinterpret_cast<const float2*>(&g_zsil[m * DINNER + nb]);
                    float bc  = sbc[m - m0];
                    float y0 = (dt0 * xv.x * bc + aux1[nb]     * xv.x) * zv.x;
                    float y1 = (dt1 * xv.y * bc + aux1[nb + 1] * xv.y) * zv.y;
                    *reinterpret_cast<float2*>(&C[m * DINNER + nb]) = make_float2(y0, y1);
                }
            }
        }
    }
}

// out[b] = sigmoid( dot(h1[b], fc5_w) + fc5_b )
__global__ void fc5_kernel(const float* __restrict__ w,
                           const float* __restrict__ bias,
                           float* __restrict__ out)
{
    const int b = blockIdx.x;
    const int t = threadIdx.x;  // 256
    float v = g_h1[b * HIDDEN + t] * w[t];
    #pragma unroll
    for (int o = 16; o > 0; o >>= 1) v += __shfl_xor_sync(0xFFFFFFFFu, v, o);
    __shared__ float ws[8];
    if ((t & 31) == 0) ws[t >> 5] = v;
    __syncthreads();
    if (t == 0) {
        float s = bias[0];
        #pragma unroll
        for (int i = 0; i < 8; i++) s += ws[i];
        out[b] = 1.f / (1.f + __expf(-s));
    }
}

extern "C" void kernel_launch(void* const* d_in, const int* in_sizes, int n_in,
                              void* d_out, int out_size)
{
    const float* x         = (const float*)d_in[0];
    const float* in_proj_w = (const float*)d_in[1];
    const float* conv_w    = (const float*)d_in[2];
    const float* conv_b    = (const float*)d_in[3];
    const float* x_proj_w  = (const float*)d_in[4];
    const float* dt_proj_w = (const float*)d_in[5];
    const float* dt_proj_b = (const float*)d_in[6];
    // d_in[7] = A_log: dead (h0 = 0, L = 1)
    const float* Dp        = (const float*)d_in[8];
    const float* out_projw = (const float*)d_in[9];
    const float* fc1_w     = (const float*)d_in[10];
    const float* fc1_b     = (const float*)d_in[11];
    const float* fc5_w     = (const float*)d_in[12];
    const float* fc5_b     = (const float*)d_in[13];
    float* out = (float*)d_out;

    float *xin, *zsil, *xdbl, *y, *out1, *h1;
    cudaGetSymbolAddress((void**)&xin,  g_xin);
    cudaGetSymbolAddress((void**)&zsil, g_zsil);
    cudaGetSymbolAddress((void**)&xdbl, g_xdbl);
    cudaGetSymbolAddress((void**)&y,    g_y);
    cudaGetSymbolAddress((void**)&out1, g_out1);
    cudaGetSymbolAddress((void**)&h1,   g_h1);

    const dim3 blk(128);
    // 1. in_proj (N=2048,K=512) + conv + silu split        [grid 64x8 = 512]
    gemm_v4<2><<<dim3(2048/32, BB/64), blk>>>(x, DMODEL, in_proj_w, xin,
                                              2*DINNER, DMODEL, conv_b, conv_w, zsil);
    // 2. x_proj (N=288,K=1024) -> xdbl                     [grid 9x8 = 72]
    gemm_v4<0><<<dim3(XDBL_W/32, BB/64), blk>>>(xin, DINNER, x_proj_w, xdbl,
                                                XDBL_W, DINNER, nullptr, nullptr, nullptr);
    // 3. dt_proj (N=1024,K=32) + inline bc + y             [grid 32x8 = 256]
    gemm_v4<3><<<dim3(DINNER/32, BB/64), blk>>>(xdbl, XDBL_W, dt_proj_w, y,
                                                DINNER, DTRANK, dt_proj_b, Dp, nullptr);
    // 4. out_proj (N=512,K=1024) -> out1                   [grid 16x8 = 128]
    gemm_v4<0><<<dim3(DMODEL/32, BB/64), blk>>>(y, DINNER, out_projw, out1,
                                                DMODEL, DINNER, nullptr, nullptr, nullptr);
    // 5. fc1 (N=256,K=512) + bias + leaky -> h1            [grid 8x8 = 64]
    gemm_v4<1><<<dim3(HIDDEN/32, BB/64), blk>>>(out1, DMODEL, fc1_w, h1,
                                                HIDDEN, DMODEL, fc1_b, nullptr, nullptr);
    // 6. fc5 + sigmoid -> out (B,1)
    fc5_kernel<<<BB, 256>>>(fc5_w, fc5_b, out);
}

// round 5
// speedup vs baseline: 1.0039x; 1.0039x over previous
#include <cuda_runtime.h>
#include <math.h>
#include <stdint.h>

// L = 1 collapses the Mamba scan: h = dBu, y = dt*xin*(Bm.Cm) + D*xin, A_log dead.
#define BB      512
#define DMODEL  512
#define DSTATE  128
#define DINNER  1024
#define DTRANK  32
#define HIDDEN  256
#define XDBL_W  (DTRANK + 2*DSTATE)   // 288

// -------- scratch (no allocations allowed; __device__ globals) --------
__device__ float g_xin  [BB*DINNER];
__device__ float g_zsil [BB*DINNER];
__device__ float g_xdblp[4*BB*XDBL_W];   // x_proj split-K partial planes
__device__ float g_opart[4*BB*DMODEL];   // out_proj split-K partial planes
__device__ float g_y    [BB*DINNER];
__device__ float g_out1 [BB*DMODEL];
__device__ float g_h1   [BB*HIDDEN];

__device__ __forceinline__ float siluf(float x) { return x / (1.f + __expf(-x)); }

__device__ __forceinline__ void mma_tf32(float c[4],
                                         unsigned a0, unsigned a1, unsigned a2, unsigned a3,
                                         unsigned b0, unsigned b1)
{
    asm volatile(
        "mma.sync.aligned.m16n8k8.row.col.f32.tf32.tf32.f32 "
        "{%0,%1,%2,%3}, {%4,%5,%6,%7}, {%8,%9}, {%0,%1,%2,%3};"
        : "+f"(c[0]), "+f"(c[1]), "+f"(c[2]), "+f"(c[3])
        : "r"(a0), "r"(a1), "r"(a2), "r"(a3), "r"(b0), "r"(b1));
}

__device__ __forceinline__ void cp16(void* smem, const void* gmem)
{
    unsigned sa = (unsigned)__cvta_generic_to_shared(smem);
    asm volatile("cp.async.cg.shared.global [%0], [%1], 16;" :: "r"(sa), "l"(gmem));
}

// ---------------------------------------------------------------------
// tf32 GEMM, 3-stage cp.async, BM=64, BN=32, BK=32, 128 thr = 4 warps,
// warp tile 32x16 (4 independent MMA chains).
// SPLITZ > 1: blockIdx.z selects K-slice; C -> partial plane z (stride cplane).
// SUMA  > 1 : A tile = sum of SUMA partial planes (stride aplane); sync loads.
// MODE 0: plain store        MODE 1: +bias, leaky-relu 0.1
// MODE 2: in_proj split (silu(conv) / silu -> out2)
// MODE 3: inline bc = Bm.Cm (on summed A); dt=softplus; y=(dt*xin*bc+D*xin)*zsil
// ---------------------------------------------------------------------
template<int MODE, int SPLITZ, int SUMA>
__global__ void __launch_bounds__(128)
gemm_v5(const float* __restrict__ A, int lda, long aplane,
        const float* __restrict__ W, int ldw,
        float* __restrict__ C, int N, int K, long cplane,
        const float* __restrict__ aux0,
        const float* __restrict__ aux1,
        float* __restrict__ out2)
{
    constexpr int BM  = 64;
    constexpr int BN  = 32;
    constexpr int BK  = 32;
    constexpr int LDS = BK + 4;        // stride 36: conflict-free frag LDS
    constexpr int NST = 3;

    __shared__ float As[NST][BM][LDS];
    __shared__ float Ws[NST][BN][LDS];
    __shared__ float sbc[BM];

    const int tid  = threadIdx.x;
    const int lane = tid & 31;
    const int wid  = tid >> 5;
    const int wm   = wid & 1;
    const int wn   = wid >> 1;
    const int g    = lane >> 2;
    const int t    = lane & 3;
    const int m0   = blockIdx.y * BM;
    const int n0   = blockIdx.x * BN;

    const int z = (SPLITZ > 1) ? blockIdx.z : 0;
    const float* Az = A + (long)z * K;          // K = slice length; lda = full row stride
    const float* Wz = W + (long)z * K;          // ldw = full row stride
    float* Cz = C + ((SPLITZ > 1) ? (long)z * cplane : 0L);

    const int arow = tid >> 3;         // 0..15
    const int acol = (tid & 7) * 4;    // 0,4,...,28

    // MODE3: bc[r] = dot(Bm, Cm) of the SUMMED planes (A = g_xdblp, lda = XDBL_W)
    if (MODE == 3) {
        #pragma unroll
        for (int rr = 0; rr < 16; ++rr) {
            const int r = wid * 16 + rr;
            const long base = (long)(m0 + r) * lda;
            float v = 0.f;
            #pragma unroll
            for (int i = 0; i < DSTATE / 32; ++i) {
                float a = 0.f, b = 0.f;
                #pragma unroll
                for (int p = 0; p < SUMA; ++p) {
                    a += A[p*aplane + base + DTRANK + lane + 32*i];
                    b += A[p*aplane + base + DTRANK + DSTATE + lane + 32*i];
                }
                v += a * b;
            }
            #pragma unroll
            for (int o = 16; o > 0; o >>= 1) v += __shfl_xor_sync(0xFFFFFFFFu, v, o);
            if (lane == 0) sbc[r] = v;
        }
    }

    const int NK = K / BK;

    auto load_tiles = [&](int kt, int buf) {
        const int k0 = kt * BK;
        if (SUMA == 1) {
            #pragma unroll
            for (int r = 0; r < 4; ++r)
                cp16(&As[buf][arow + 16*r][acol], &Az[(long)(m0 + arow + 16*r) * lda + k0 + acol]);
        } else {
            #pragma unroll
            for (int r = 0; r < 4; ++r) {
                const long base = (long)(m0 + arow + 16*r) * lda + k0 + acol;
                float4 s = make_float4(0.f, 0.f, 0.f, 0.f);
                #pragma unroll
                for (int p = 0; p < SUMA; ++p) {
                    float4 v = *reinterpret_cast<const float4*>(&A[p*aplane + base]);
                    s.x += v.x; s.y += v.y; s.z += v.z; s.w += v.w;
                }
                *reinterpret_cast<float4*>(&As[buf][arow + 16*r][acol]) = s;
            }
        }
        #pragma unroll
        for (int r = 0; r < 2; ++r)
            cp16(&Ws[buf][arow + 16*r][acol], &Wz[(long)(n0 + arow + 16*r) * ldw + k0 + acol]);
    };

    float acc[2][2][4] = {};

    load_tiles(0, 0);
    asm volatile("cp.async.commit_group;");
    if (NK > 1) {
        load_tiles(1, 1);
        asm volatile("cp.async.commit_group;");
    }

    for (int it = 0; it < NK; ++it) {
        if (it + 1 < NK) asm volatile("cp.async.wait_group 1;");
        else             asm volatile("cp.async.wait_group 0;");
        __syncthreads();

        if (it + 2 < NK) {
            load_tiles(it + 2, (it + 2) % NST);
            asm volatile("cp.async.commit_group;");
        }

        const int buf = it % NST;
        #pragma unroll
        for (int ks = 0; ks < BK / 8; ++ks) {
            const int kk = ks * 8 + t;
            unsigned b0[2], b1[2];
            #pragma unroll
            for (int nt = 0; nt < 2; ++nt) {
                const int br = wn * 16 + nt * 8 + g;
                b0[nt] = __float_as_uint(Ws[buf][br][kk]);
                b1[nt] = __float_as_uint(Ws[buf][br][kk + 4]);
            }
            #pragma unroll
            for (int mt = 0; mt < 2; ++mt) {
                const int ar = wm * 32 + mt * 16 + g;
                unsigned a0 = __float_as_uint(As[buf][ar    ][kk]);
                unsigned a1 = __float_as_uint(As[buf][ar + 8][kk]);
                unsigned a2 = __float_as_uint(As[buf][ar    ][kk + 4]);
                unsigned a3 = __float_as_uint(As[buf][ar + 8][kk + 4]);
                #pragma unroll
                for (int nt = 0; nt < 2; ++nt)
                    mma_tf32(acc[mt][nt], a0, a1, a2, a3, b0[nt], b1[nt]);
            }
        }
    }

    // ---- epilogue ----
    #pragma unroll
    for (int mt = 0; mt < 2; ++mt) {
        #pragma unroll
        for (int nt = 0; nt < 2; ++nt) {
            const int nb = n0 + wn * 16 + nt * 8 + 2 * t;
            #pragma unroll
            for (int half = 0; half < 2; ++half) {
                const int m = m0 + wm * 32 + mt * 16 + g + 8 * half;
                float v0 = acc[mt][nt][2*half + 0];
                float v1 = acc[mt][nt][2*half + 1];
                if (MODE == 0) {
                    *reinterpret_cast<float2*>(&Cz[(long)m * N + nb]) = make_float2(v0, v1);
                } else if (MODE == 1) {
                    v0 += aux0[nb]; v1 += aux0[nb + 1];
                    v0 = (v0 >= 0.f) ? v0 : 0.1f * v0;
                    v1 = (v1 >= 0.f) ? v1 : 0.1f * v1;
                    *reinterpret_cast<float2*>(&Cz[(long)m * N + nb]) = make_float2(v0, v1);
                } else if (MODE == 2) {
                    if (n0 < DINNER) {
                        float c0 = aux0[nb]     + aux1[2*nb + 1]     * v0;
                        float c1 = aux0[nb + 1] + aux1[2*(nb+1) + 1] * v1;
                        *reinterpret_cast<float2*>(&Cz[(long)m * DINNER + nb]) =
                            make_float2(siluf(c0), siluf(c1));
                    } else {
                        *reinterpret_cast<float2*>(&out2[(long)m * DINNER + nb - DINNER]) =
                            make_float2(siluf(v0), siluf(v1));
                    }
                } else { // MODE 3
                    v0 += aux0[nb]; v1 += aux0[nb + 1];
                    float dt0 = (v0 > 20.f) ? v0 : log1pf(__expf(v0));
                    float dt1 = (v1 > 20.f) ? v1 : log1pf(__expf(v1));
                    float2 xv = *reinterpret_cast<const float2*>(&g_xin [(long)m * DINNER + nb]);
                    float2 zv = *reinterpret_cast<const float2*>(&g_zsil[(long)m * DINNER + nb]);
                    float bc  = sbc[m - m0];
                    float y0 = (dt0 * xv.x * bc + aux1[nb]     * xv.x) * zv.x;
                    float y1 = (dt1 * xv.y * bc + aux1[nb + 1] * xv.y) * zv.y;
                    *reinterpret_cast<float2*>(&Cz[(long)m * DINNER + nb]) = make_float2(y0, y1);
                }
            }
        }
    }
}

// out1 = p0 + p1 + p2 + p3 (fixed order, deterministic); float4, 256K elems
__global__ void reduce4_kernel()
{
    const int i = blockIdx.x * blockDim.x + threadIdx.x;   // 65536 float4s
    const float4* p = reinterpret_cast<const float4*>(g_opart);
    const long plane4 = (long)BB * DMODEL / 4;
    float4 a = p[i], b = p[i + plane4], c = p[i + 2*plane4], d = p[i + 3*plane4];
    float4 o = make_float4(a.x+b.x+c.x+d.x, a.y+b.y+c.y+d.y,
                           a.z+b.z+c.z+d.z, a.w+b.w+c.w+d.w);
    reinterpret_cast<float4*>(g_out1)[i] = o;
}

// out[b] = sigmoid( dot(h1[b], fc5_w) + fc5_b )
__global__ void fc5_kernel(const float* __restrict__ w,
                           const float* __restrict__ bias,
                           float* __restrict__ out)
{
    const int b = blockIdx.x;
    const int t = threadIdx.x;  // 256
    float v = g_h1[b * HIDDEN + t] * w[t];
    #pragma unroll
    for (int o = 16; o > 0; o >>= 1) v += __shfl_xor_sync(0xFFFFFFFFu, v, o);
    __shared__ float ws[8];
    if ((t & 31) == 0) ws[t >> 5] = v;
    __syncthreads();
    if (t == 0) {
        float s = bias[0];
        #pragma unroll
        for (int i = 0; i < 8; i++) s += ws[i];
        out[b] = 1.f / (1.f + __expf(-s));
    }
}

extern "C" void kernel_launch(void* const* d_in, const int* in_sizes, int n_in,
                              void* d_out, int out_size)
{
    const float* x         = (const float*)d_in[0];
    const float* in_proj_w = (const float*)d_in[1];
    const float* conv_w    = (const float*)d_in[2];
    const float* conv_b    = (const float*)d_in[3];
    const float* x_proj_w  = (const float*)d_in[4];
    const float* dt_proj_w = (const float*)d_in[5];
    const float* dt_proj_b = (const float*)d_in[6];
    // d_in[7] = A_log: dead (h0 = 0, L = 1)
    const float* Dp        = (const float*)d_in[8];
    const float* out_projw = (const float*)d_in[9];
    const float* fc1_w     = (const float*)d_in[10];
    const float* fc1_b     = (const float*)d_in[11];
    const float* fc5_w     = (const float*)d_in[12];
    const float* fc5_b     = (const float*)d_in[13];
    float* out = (float*)d_out;

    float *xin, *zsil, *xdblp, *opart, *y, *out1, *h1;
    cudaGetSymbolAddress((void**)&xin,   g_xin);
    cudaGetSymbolAddress((void**)&zsil,  g_zsil);
    cudaGetSymbolAddress((void**)&xdblp, g_xdblp);
    cudaGetSymbolAddress((void**)&opart, g_opart);
    cudaGetSymbolAddress((void**)&y,     g_y);
    cudaGetSymbolAddress((void**)&out1,  g_out1);
    cudaGetSymbolAddress((void**)&h1,    g_h1);

    const dim3 blk(128);
    const long XP = (long)BB * XDBL_W;   // xdbl plane
    const long OP = (long)BB * DMODEL;   // out1 plane

    // 1. in_proj (N=2048,K=512) + conv + silu split          [512 CTAs]
    gemm_v5<2,1,1><<<dim3(64, 8), blk>>>(x, DMODEL, 0, in_proj_w, DMODEL,
                                         xin, 2*DINNER, DMODEL, 0, conv_b, conv_w, zsil);
    // 2. x_proj split-K x4 (slices K=256) -> xdbl partials   [288 CTAs]
    gemm_v5<0,4,1><<<dim3(9, 8, 4), blk>>>(xin, DINNER, 0, x_proj_w, DINNER,
                                           xdblp, XDBL_W, DINNER/4, XP, nullptr, nullptr, nullptr);
    // 3. dt_proj (K=32) on summed planes + bc + y            [256 CTAs]
    gemm_v5<3,1,4><<<dim3(32, 8), blk>>>(xdblp, XDBL_W, XP, dt_proj_w, DTRANK,
                                         y, DINNER, DTRANK, 0, dt_proj_b, Dp, nullptr);
    // 4. out_proj split-K x4 -> out1 partials                [512 CTAs]
    gemm_v5<0,4,1><<<dim3(16, 8, 4), blk>>>(y, DINNER, 0, out_projw, DINNER,
                                            opart, DMODEL, DINNER/4, OP, nullptr, nullptr, nullptr);
    // 5. out1 = sum of 4 planes
    reduce4_kernel<<<256, 256>>>();
    // 6. fc1 (N=256,K=512) + bias + leaky -> h1              [64 CTAs]
    gemm_v5<1,1,1><<<dim3(8, 8), blk>>>(out1, DMODEL, 0, fc1_w, DMODEL,
                                        h1, HIDDEN, DMODEL, 0, fc1_b, nullptr, nullptr);
    // 7. fc5 + sigmoid -> out (B,1)
    fc5_kernel<<<BB, 256>>>(fc5_w, fc5_b, out);
}